// round 2
// baseline (speedup 1.0000x reference)
#include <cuda_runtime.h>
#include <math.h>

#define B 32
#define N 512
#define FIN 16
#define H 8
#define DH 8
#define DOUT 32

// ---------------- scratch (static device arrays; no allocation) ----------------
__device__ float g_Wh[B*H*N*DH];          // [b][h][n][d]    4 MB
__device__ float g_f1[B*H*N];
__device__ float g_f2[B*H*N];
__device__ float g_hcat[B*N*H*DH];        // [b][n][h*8+d]   4 MB
__device__ float g_Who[B*N*DOUT];         // [b][n][d]       2 MB
__device__ float g_g1[B*N];
__device__ float g_g2[B*N];
__device__ float g_out[B*N*DOUT];         // post-elu, [b][n*32+d] = [b][k]
__device__ float g_qpart[64*B*N];         // split-K partials

// ---------------- helpers ----------------
__device__ __forceinline__ float warpSum(float v){
#pragma unroll
    for (int o = 16; o; o >>= 1) v += __shfl_xor_sync(0xffffffffu, v, o);
    return v;
}
__device__ __forceinline__ float warpMax(float v){
#pragma unroll
    for (int o = 16; o; o >>= 1) v = fmaxf(v, __shfl_xor_sync(0xffffffffu, v, o));
    return v;
}
__device__ __forceinline__ float lrelu(float x){ return x >= 0.f ? x : 0.2f * x; }
__device__ __forceinline__ float elu(float x){ return x > 0.f ? x : expm1f(x); }

// ---------------- K1: Wh = xv @ W_heads ; f1 = Wh.a1 ; f2 = Wh.a2 ----------------
__global__ void k1_proj(const float* __restrict__ xv,
                        const float* __restrict__ Wheads,
                        const float* __restrict__ a1,
                        const float* __restrict__ a2){
    __shared__ float Ws[H*FIN*DH];      // 1024 floats
    __shared__ float a1s[H*DH], a2s[H*DH];
    int t = threadIdx.x;
    for (int i = t; i < H*FIN*DH; i += 256) Ws[i] = Wheads[i];
    if (t < H*DH){ a1s[t] = a1[t]; a2s[t] = a2[t]; }
    __syncthreads();

    int gt = blockIdx.x * 256 + t;      // 131072 threads total
    int h  = gt & 7;
    int bn = gt >> 3;                   // [0, B*N)
    const float* xr = xv + bn * FIN;

    float wh[DH];
#pragma unroll
    for (int d = 0; d < DH; d++) wh[d] = 0.f;
#pragma unroll
    for (int f = 0; f < FIN; f++){
        float x = xr[f];
        const float* wf = Ws + (h*FIN + f)*DH;
#pragma unroll
        for (int d = 0; d < DH; d++) wh[d] += x * wf[d];
    }
    float f1v = 0.f, f2v = 0.f;
#pragma unroll
    for (int d = 0; d < DH; d++){
        f1v += wh[d] * a1s[h*DH + d];
        f2v += wh[d] * a2s[h*DH + d];
    }
    int b = bn >> 9, n = bn & 511;
    int bh = b*H + h;
    float* dst = g_Wh + ((size_t)bh * N + n) * DH;
    ((float4*)dst)[0] = make_float4(wh[0], wh[1], wh[2], wh[3]);
    ((float4*)dst)[1] = make_float4(wh[4], wh[5], wh[6], wh[7]);
    g_f1[bh*N + n] = f1v;
    g_f2[bh*N + n] = f2v;
}

// ---------------- K2: layer-1 masked softmax + aggregation, 8 heads / block ----------------
__global__ void k2_gat(const float* __restrict__ adj){
    __shared__ int  jlist[N];
    __shared__ int  s_cnt;
    int bi = blockIdx.x;            // = b*512 + i
    int t = threadIdx.x, w = t >> 5, lane = t & 31;

    if (w == 0){
        const float* arow = adj + (size_t)bi * N;
        int base = 0;
        for (int c = 0; c < N/32; c++){
            float a = arow[c*32 + lane];
            unsigned bal = __ballot_sync(0xffffffffu, a > 0.f);
            if (a > 0.f) jlist[base + __popc(bal & ((1u << lane) - 1u))] = c*32 + lane;
            base += __popc(bal);
        }
        if (lane == 0) s_cnt = base;
    }
    __syncthreads();
    int cnt = s_cnt;

    int b = bi >> 9, i = bi & 511;
    int bh = b*H + w;                       // warp = head
    const float* f2h = g_f2 + bh * N;
    const float* WhB = g_Wh + (size_t)bh * N * DH;
    float f1i = g_f1[bh*N + i];

    float s = 0.f;
    float pacc[DH];
#pragma unroll
    for (int d = 0; d < DH; d++) pacc[d] = 0.f;

    if (cnt > 0){
        float m = -1e30f;
        for (int k = lane; k < cnt; k += 32)
            m = fmaxf(m, lrelu(f1i + f2h[jlist[k]]));
        m = warpMax(m);
        for (int k = lane; k < cnt; k += 32){
            int j = jlist[k];
            float p = expf(lrelu(f1i + f2h[j]) - m);
            s += p;
            float4 wa = ((const float4*)(WhB + j*DH))[0];
            float4 wb = ((const float4*)(WhB + j*DH))[1];
            pacc[0] += p*wa.x; pacc[1] += p*wa.y; pacc[2] += p*wa.z; pacc[3] += p*wa.w;
            pacc[4] += p*wb.x; pacc[5] += p*wb.y; pacc[6] += p*wb.z; pacc[7] += p*wb.w;
        }
    } else {
        // all masked out -> softmax over uniform scores = 1/N each
        for (int j = lane; j < N; j += 32){
            s += 1.f;
            float4 wa = ((const float4*)(WhB + j*DH))[0];
            float4 wb = ((const float4*)(WhB + j*DH))[1];
            pacc[0] += wa.x; pacc[1] += wa.y; pacc[2] += wa.z; pacc[3] += wa.w;
            pacc[4] += wb.x; pacc[5] += wb.y; pacc[6] += wb.z; pacc[7] += wb.w;
        }
    }
    s = warpSum(s);
#pragma unroll
    for (int d = 0; d < DH; d++) pacc[d] = warpSum(pacc[d]);

    if (lane == 0){
        float inv = 1.f / s;
        float r0 = elu(pacc[0]*inv), r1 = elu(pacc[1]*inv), r2 = elu(pacc[2]*inv), r3 = elu(pacc[3]*inv);
        float r4 = elu(pacc[4]*inv), r5 = elu(pacc[5]*inv), r6 = elu(pacc[6]*inv), r7 = elu(pacc[7]*inv);
        float* o = g_hcat + (size_t)bi * (H*DH) + w * DH;
        ((float4*)o)[0] = make_float4(r0, r1, r2, r3);
        ((float4*)o)[1] = make_float4(r4, r5, r6, r7);
    }
}

// ---------------- K3: Who = h_cat @ W_out ; g1 = Who.a1_out ; g2 = Who.a2_out ----------------
__global__ void k3_who(const float* __restrict__ Wout,
                       const float* __restrict__ a1o,
                       const float* __restrict__ a2o){
    __shared__ float Ws[64*32];    // 8 KB
    __shared__ float hs[8*64];     // 8 rows of h_cat
    __shared__ float a1s[32], a2s[32];
    int t = threadIdx.x;
    for (int i = t; i < 64*32; i += 256) Ws[i] = Wout[i];
    if (t < 32){ a1s[t] = a1o[t]; a2s[t] = a2o[t]; }
    for (int i = t; i < 8*64; i += 256) hs[i] = g_hcat[(size_t)blockIdx.x*512 + i];
    __syncthreads();

    int r = t >> 5, lane = t & 31;
    int row = blockIdx.x * 8 + r;       // (b,n) flat
    float who = 0.f;
#pragma unroll
    for (int f = 0; f < 64; f++) who += hs[r*64 + f] * Ws[f*32 + lane];
    g_Who[(size_t)row*32 + lane] = who;
    float v1 = warpSum(who * a1s[lane]);
    float v2 = warpSum(who * a2s[lane]);
    if (lane == 0){ g_g1[row] = v1; g_g2[row] = v2; }
}

// ---------------- K4: layer-2 masked softmax + aggregation (warp per row) ----------------
__global__ void k4_outattn(const float* __restrict__ adj){
    __shared__ int   jl[4][N];
    __shared__ float tr[4][32*33];
    int t = threadIdx.x, w = t >> 5, lane = t & 31;
    int row = blockIdx.x * 4 + w;       // = b*512 + i
    int b = row >> 9;

    const float* arow = adj + (size_t)row * N;
    int base = 0;
    for (int c = 0; c < N/32; c++){
        float a = arow[c*32 + lane];
        unsigned bal = __ballot_sync(0xffffffffu, a > 0.f);
        if (a > 0.f) jl[w][base + __popc(bal & ((1u << lane) - 1u))] = c*32 + lane;
        base += __popc(bal);
    }
    int cnt = base;
    __syncwarp();

    float g1i = g_g1[row];
    const float* g2b  = g_g2 + b * N;
    const float* WhoB = g_Who + (size_t)b * N * DOUT;

    float s = 0.f;
    float pacc[DOUT];
#pragma unroll
    for (int d = 0; d < DOUT; d++) pacc[d] = 0.f;

    if (cnt > 0){
        float m = -1e30f;
        for (int k = lane; k < cnt; k += 32)
            m = fmaxf(m, lrelu(g1i + g2b[jl[w][k]]));
        m = warpMax(m);
        for (int k = lane; k < cnt; k += 32){
            int j = jl[w][k];
            float p = expf(lrelu(g1i + g2b[j]) - m);
            s += p;
            const float4* wr = (const float4*)(WhoB + (size_t)j*DOUT);
#pragma unroll
            for (int q = 0; q < 8; q++){
                float4 v = wr[q];
                pacc[4*q+0] += p*v.x; pacc[4*q+1] += p*v.y;
                pacc[4*q+2] += p*v.z; pacc[4*q+3] += p*v.w;
            }
        }
    } else {
        for (int j = lane; j < N; j += 32){
            s += 1.f;
            const float4* wr = (const float4*)(WhoB + (size_t)j*DOUT);
#pragma unroll
            for (int q = 0; q < 8; q++){
                float4 v = wr[q];
                pacc[4*q+0] += v.x; pacc[4*q+1] += v.y;
                pacc[4*q+2] += v.z; pacc[4*q+3] += v.w;
            }
        }
    }
    s = warpSum(s);

    // transpose-reduce: each lane holds partial pacc[0..31]; sum across lanes per d
    float* trw = tr[w];
#pragma unroll
    for (int d = 0; d < 32; d++) trw[lane*33 + d] = pacc[d];
    __syncwarp();
    float tot = 0.f;
#pragma unroll
    for (int l = 0; l < 32; l++) tot += trw[l*33 + lane];

    g_out[(size_t)row*DOUT + lane] = elu(tot / s);
}

// ---------------- K5: q_part = out[B,16384] @ W_q[16384,512] (split-K) ----------------
// block: 64 cols x 4 k-groups; smem holds out tile transposed [k][b] (pad 36)
__global__ void k5_qgemm(const float* __restrict__ Wq){
    __shared__ float sm[256*36];        // 36 KB
    int t = threadIdx.x;
    int c = blockIdx.x * 64 + (t & 63);
    int g = t >> 6;                     // 0..3
    float acc[32];
#pragma unroll
    for (int b = 0; b < 32; b++) acc[b] = 0.f;

    int kb0 = blockIdx.y * 1024;
    for (int st = 0; st < 4; st++){
        int kbase = kb0 + st*256;
        __syncthreads();
        // stage out[b][kbase..kbase+255] -> sm[kk][b] (coalesced float4 reads)
        for (int idx = t; idx < 2048; idx += 256){
            int b  = idx >> 6;          // 64 float4 per b
            int kq = idx & 63;
            float4 v = *(const float4*)(g_out + (size_t)b*16384 + kbase + kq*4);
            float* dst = sm + kq*4*36 + b;
            dst[0]   = v.x; dst[36]  = v.y; dst[72]  = v.z; dst[108] = v.w;
        }
        __syncthreads();

        const float* wq  = Wq + (size_t)(kbase + g*64)*512 + c;
        const float* smg = sm + (g*64)*36;
#pragma unroll 4
        for (int kk = 0; kk < 64; kk++){
            float wv = wq[(size_t)kk*512];
            const float4* o4 = (const float4*)(smg + kk*36);   // 144B stride: 16B aligned
#pragma unroll
            for (int q = 0; q < 8; q++){
                float4 o = o4[q];
                acc[4*q+0] += o.x*wv; acc[4*q+1] += o.y*wv;
                acc[4*q+2] += o.z*wv; acc[4*q+3] += o.w*wv;
            }
        }
    }
    float* qp = g_qpart + (size_t)(blockIdx.y*4 + g) * (B*N);
#pragma unroll
    for (int b = 0; b < 32; b++) qp[b*N + c] = acc[b];   // coalesced per b
}

// ---------------- K6: q = sum of 64 partials + b_q ----------------
__global__ void k6_reduce(const float* __restrict__ bq, float* __restrict__ q){
    int t = blockIdx.x * 256 + threadIdx.x;   // [0, 16384)
    int c = t & 511;
    float s = bq[c];
#pragma unroll
    for (int p = 0; p < 64; p++) s += g_qpart[p*(B*N) + t];
    q[t] = s;
}

// ---------------- launch ----------------
extern "C" void kernel_launch(void* const* d_in, const int* in_sizes, int n_in,
                              void* d_out, int out_size){
    const float* xv    = (const float*)d_in[0];
    const float* adj   = (const float*)d_in[1];
    const float* Whead = (const float*)d_in[2];
    const float* a1    = (const float*)d_in[3];
    const float* a2    = (const float*)d_in[4];
    const float* Wout  = (const float*)d_in[5];
    const float* a1o   = (const float*)d_in[6];
    const float* a2o   = (const float*)d_in[7];
    const float* Wq    = (const float*)d_in[8];
    const float* bq    = (const float*)d_in[9];
    float* q = (float*)d_out;

    k1_proj   <<<512, 256>>>(xv, Whead, a1, a2);
    k2_gat    <<<B*N, 256>>>(adj);
    k3_who    <<<B*N/8, 256>>>(Wout, a1o, a2o);
    k4_outattn<<<B*N/4, 128>>>(adj);
    k5_qgemm  <<<dim3(8, 16), 256>>>(Wq);
    k6_reduce <<<64, 256>>>(bq, q);
}

// round 3
// speedup vs baseline: 1.2346x; 1.2346x over previous
#include <cuda_runtime.h>
#include <math.h>

#define B 32
#define N 512
#define FIN 16
#define H 8
#define DH 8
#define DOUT 32

// ---------------- scratch (static device arrays; no allocation) ----------------
__device__ float g_Wh[B*H*N*DH];          // [b][h][n][d]
__device__ float g_f1[B*H*N];
__device__ float g_f2[B*H*N];
__device__ float g_hcat[B*N*H*DH];        // [b][n][h*8+d]
__device__ float g_Who[B*N*DOUT];         // [b][n][d]
__device__ float g_g1[B*N];
__device__ float g_g2[B*N];
__device__ float g_out[B*N*DOUT];         // post-elu, [b][n*32+d] = [b][k]
__device__ float g_qpart[128*B*N];        // split-K partials
__device__ int   g_cnt[B*N];              // neighbor counts
__device__ int   g_nbr[B*N*N];            // compacted neighbor lists (33.5 MB)

// ---------------- helpers ----------------
__device__ __forceinline__ float warpSum(float v){
#pragma unroll
    for (int o = 16; o; o >>= 1) v += __shfl_xor_sync(0xffffffffu, v, o);
    return v;
}
__device__ __forceinline__ float warpMax(float v){
#pragma unroll
    for (int o = 16; o; o >>= 1) v = fmaxf(v, __shfl_xor_sync(0xffffffffu, v, o));
    return v;
}
__device__ __forceinline__ float lrelu(float x){ return x >= 0.f ? x : 0.2f * x; }
__device__ __forceinline__ float elu(float x){ return x > 0.f ? x : expm1f(x); }

// ---------------- K0: compact adjacency rows into neighbor lists ----------------
// warp per row; all 16 loads issued before any ballot (MLP=16)
__global__ void k0_compact(const float* __restrict__ adj){
    int t = threadIdx.x, w = t >> 5, lane = t & 31;
    int row = blockIdx.x * 8 + w;
    const float* arow = adj + (size_t)row * N;
    float av[16];
#pragma unroll
    for (int c = 0; c < 16; c++) av[c] = arow[c*32 + lane];
    unsigned bal[16];
#pragma unroll
    for (int c = 0; c < 16; c++) bal[c] = __ballot_sync(0xffffffffu, av[c] > 0.f);
    int* dst = g_nbr + (size_t)row * N;
    int base = 0;
    unsigned lmask = (1u << lane) - 1u;
#pragma unroll
    for (int c = 0; c < 16; c++){
        unsigned b = bal[c];
        if ((b >> lane) & 1u) dst[base + __popc(b & lmask)] = c*32 + lane;
        base += __popc(b);
    }
    if (lane == 0) g_cnt[row] = base;
}

// ---------------- K1: Wh = xv @ W_heads ; f1 = Wh.a1 ; f2 = Wh.a2 ----------------
__global__ void k1_proj(const float* __restrict__ xv,
                        const float* __restrict__ Wheads,
                        const float* __restrict__ a1,
                        const float* __restrict__ a2){
    __shared__ float Ws[H*FIN*DH];
    __shared__ float a1s[H*DH], a2s[H*DH];
    int t = threadIdx.x;
    for (int i = t; i < H*FIN*DH; i += 256) Ws[i] = Wheads[i];
    if (t < H*DH){ a1s[t] = a1[t]; a2s[t] = a2[t]; }
    __syncthreads();

    int gt = blockIdx.x * 256 + t;
    int h  = gt & 7;
    int bn = gt >> 3;
    const float* xr = xv + bn * FIN;

    float wh[DH];
#pragma unroll
    for (int d = 0; d < DH; d++) wh[d] = 0.f;
#pragma unroll
    for (int f = 0; f < FIN; f++){
        float x = xr[f];
        const float* wf = Ws + (h*FIN + f)*DH;
#pragma unroll
        for (int d = 0; d < DH; d++) wh[d] += x * wf[d];
    }
    float f1v = 0.f, f2v = 0.f;
#pragma unroll
    for (int d = 0; d < DH; d++){
        f1v += wh[d] * a1s[h*DH + d];
        f2v += wh[d] * a2s[h*DH + d];
    }
    int b = bn >> 9, n = bn & 511;
    int bh = b*H + h;
    float* dstp = g_Wh + ((size_t)bh * N + n) * DH;
    ((float4*)dstp)[0] = make_float4(wh[0], wh[1], wh[2], wh[3]);
    ((float4*)dstp)[1] = make_float4(wh[4], wh[5], wh[6], wh[7]);
    g_f1[bh*N + n] = f1v;
    g_f2[bh*N + n] = f2v;
}

// ---------------- K2: layer-1 masked softmax + aggregation (warp = head) ----------------
__global__ void k2_gat(){
    int bi = blockIdx.x;            // = b*512 + i
    int t = threadIdx.x, w = t >> 5, lane = t & 31;
    int cnt = g_cnt[bi];
    const int* jl = g_nbr + (size_t)bi * N;

    int b = bi >> 9, i = bi & 511;
    int bh = b*H + w;
    const float* f2h = g_f2 + bh * N;
    const float* WhB = g_Wh + (size_t)bh * N * DH;
    float f1i = g_f1[bh*N + i];

    float s = 0.f;
    float pacc[DH];
#pragma unroll
    for (int d = 0; d < DH; d++) pacc[d] = 0.f;

    if (cnt > 0){
        float m = -1e30f;
        for (int k = lane; k < cnt; k += 32)
            m = fmaxf(m, lrelu(f1i + f2h[jl[k]]));
        m = warpMax(m);
        for (int k = lane; k < cnt; k += 32){
            int j = jl[k];
            float p = expf(lrelu(f1i + f2h[j]) - m);
            s += p;
            float4 wa = ((const float4*)(WhB + j*DH))[0];
            float4 wb = ((const float4*)(WhB + j*DH))[1];
            pacc[0] += p*wa.x; pacc[1] += p*wa.y; pacc[2] += p*wa.z; pacc[3] += p*wa.w;
            pacc[4] += p*wb.x; pacc[5] += p*wb.y; pacc[6] += p*wb.z; pacc[7] += p*wb.w;
        }
    } else {
        for (int j = lane; j < N; j += 32){
            s += 1.f;
            float4 wa = ((const float4*)(WhB + j*DH))[0];
            float4 wb = ((const float4*)(WhB + j*DH))[1];
            pacc[0] += wa.x; pacc[1] += wa.y; pacc[2] += wa.z; pacc[3] += wa.w;
            pacc[4] += wb.x; pacc[5] += wb.y; pacc[6] += wb.z; pacc[7] += wb.w;
        }
    }
    s = warpSum(s);
#pragma unroll
    for (int d = 0; d < DH; d++) pacc[d] = warpSum(pacc[d]);

    if (lane == 0){
        float inv = 1.f / s;
        float* o = g_hcat + (size_t)bi * (H*DH) + w * DH;
        ((float4*)o)[0] = make_float4(elu(pacc[0]*inv), elu(pacc[1]*inv), elu(pacc[2]*inv), elu(pacc[3]*inv));
        ((float4*)o)[1] = make_float4(elu(pacc[4]*inv), elu(pacc[5]*inv), elu(pacc[6]*inv), elu(pacc[7]*inv));
    }
}

// ---------------- K3: Who = h_cat @ W_out ; g1 = Who.a1_out ; g2 = Who.a2_out ----------------
__global__ void k3_who(const float* __restrict__ Wout,
                       const float* __restrict__ a1o,
                       const float* __restrict__ a2o){
    __shared__ float Ws[64*32];
    __shared__ float hs[8*64];
    __shared__ float a1s[32], a2s[32];
    int t = threadIdx.x;
    for (int i = t; i < 64*32; i += 256) Ws[i] = Wout[i];
    if (t < 32){ a1s[t] = a1o[t]; a2s[t] = a2o[t]; }
    for (int i = t; i < 8*64; i += 256) hs[i] = g_hcat[(size_t)blockIdx.x*512 + i];
    __syncthreads();

    int r = t >> 5, lane = t & 31;
    int row = blockIdx.x * 8 + r;
    float who = 0.f;
#pragma unroll
    for (int f = 0; f < 64; f++) who += hs[r*64 + f] * Ws[f*32 + lane];
    g_Who[(size_t)row*32 + lane] = who;
    float v1 = warpSum(who * a1s[lane]);
    float v2 = warpSum(who * a2s[lane]);
    if (lane == 0){ g_g1[row] = v1; g_g2[row] = v2; }
}

// ---------------- K4: layer-2 masked softmax + aggregation (warp per row, lane = dim) ----------------
__global__ void k4_outattn(){
    int t = threadIdx.x, w = t >> 5, lane = t & 31;
    int row = blockIdx.x * 8 + w;       // = b*512 + i
    int b = row >> 9;
    int cnt = g_cnt[row];
    const int* jl = g_nbr + (size_t)row * N;

    float g1i = g_g1[row];
    const float* g2b  = g_g2 + b * N;
    const float* WhoB = g_Who + (size_t)b * N * DOUT;

    float s = 0.f, tot = 0.f;
    if (cnt > 0){
        float m = -1e30f;
        for (int k = lane; k < cnt; k += 32)
            m = fmaxf(m, lrelu(g1i + g2b[jl[k]]));
        m = warpMax(m);
        for (int base = 0; base < cnt; base += 32){
            int k = base + lane;
            float p = 0.f; int j = 0;
            if (k < cnt){ j = jl[k]; p = expf(lrelu(g1i + g2b[j]) - m); }
            s += p;
            int lim = min(32, cnt - base);
            for (int kk = 0; kk < lim; kk++){
                float pb = __shfl_sync(0xffffffffu, p, kk);
                int   jb = __shfl_sync(0xffffffffu, j, kk);
                tot += pb * WhoB[(size_t)jb*DOUT + lane];
            }
        }
        s = warpSum(s);
    } else {
        s = (float)N;
        for (int j = 0; j < N; j++) tot += WhoB[(size_t)j*DOUT + lane];
    }
    g_out[(size_t)row*DOUT + lane] = elu(tot / s);
}

// ---------------- K5: q_part = out[B,16384] @ W_q[16384,512] (split-K 32-way) ----------------
__global__ void k5_qgemm(const float* __restrict__ Wq){
    __shared__ float sm[256*36];        // 36 KB
    int t = threadIdx.x;
    int c = blockIdx.x * 64 + (t & 63);
    int g = t >> 6;                     // 0..3
    float acc[32];
#pragma unroll
    for (int b = 0; b < 32; b++) acc[b] = 0.f;

    int kb0 = blockIdx.y * 512;
    for (int st = 0; st < 2; st++){
        int kbase = kb0 + st*256;
        __syncthreads();
        for (int idx = t; idx < 2048; idx += 256){
            int b  = idx >> 6;
            int kq = idx & 63;
            float4 v = *(const float4*)(g_out + (size_t)b*16384 + kbase + kq*4);
            float* dst = sm + kq*4*36 + b;
            dst[0]   = v.x; dst[36]  = v.y; dst[72]  = v.z; dst[108] = v.w;
        }
        __syncthreads();

        const float* wq  = Wq + (size_t)(kbase + g*64)*512 + c;
        const float* smg = sm + (g*64)*36;
#pragma unroll 4
        for (int kk = 0; kk < 64; kk++){
            float wv = wq[(size_t)kk*512];
            const float4* o4 = (const float4*)(smg + kk*36);
#pragma unroll
            for (int q = 0; q < 8; q++){
                float4 o = o4[q];
                acc[4*q+0] += o.x*wv; acc[4*q+1] += o.y*wv;
                acc[4*q+2] += o.z*wv; acc[4*q+3] += o.w*wv;
            }
        }
    }
    float* qp = g_qpart + (size_t)(blockIdx.y*4 + g) * (B*N);
#pragma unroll
    for (int b = 0; b < 32; b++) qp[b*N + c] = acc[b];
}

// ---------------- K6: q = sum of 128 partials + b_q ----------------
__global__ void k6_reduce(const float* __restrict__ bq, float* __restrict__ q){
    int t = blockIdx.x * 256 + threadIdx.x;   // [0, 16384)
    int c = t & 511;
    float s = bq[c];
#pragma unroll
    for (int p = 0; p < 128; p++) s += g_qpart[(size_t)p*(B*N) + t];
    q[t] = s;
}

// ---------------- launch ----------------
extern "C" void kernel_launch(void* const* d_in, const int* in_sizes, int n_in,
                              void* d_out, int out_size){
    const float* xv    = (const float*)d_in[0];
    const float* adj   = (const float*)d_in[1];
    const float* Whead = (const float*)d_in[2];
    const float* a1    = (const float*)d_in[3];
    const float* a2    = (const float*)d_in[4];
    const float* Wout  = (const float*)d_in[5];
    const float* a1o   = (const float*)d_in[6];
    const float* a2o   = (const float*)d_in[7];
    const float* Wq    = (const float*)d_in[8];
    const float* bq    = (const float*)d_in[9];
    float* q = (float*)d_out;

    k0_compact<<<B*N/8, 256>>>(adj);
    k1_proj   <<<512, 256>>>(xv, Whead, a1, a2);
    k2_gat    <<<B*N, 256>>>();
    k3_who    <<<B*N/8, 256>>>(Wout, a1o, a2o);
    k4_outattn<<<B*N/8, 256>>>();
    k5_qgemm  <<<dim3(8, 32), 256>>>(Wq);
    k6_reduce <<<64, 256>>>(bq, q);
}

// round 6
// speedup vs baseline: 1.2603x; 1.0208x over previous
#include <cuda_runtime.h>
#include <math.h>

#define B 32
#define N 512
#define FIN 16
#define H 8
#define DH 8
#define DOUT 32

typedef unsigned long long ull;

// ---------------- scratch (static device arrays; no allocation) ----------------
__device__ float g_Wh[B*H*N*DH];          // [b][h][n][d]
__device__ float g_f1[B*H*N];
__device__ float g_f2[B*H*N];
__device__ float g_hcat[B*N*H*DH];        // [b][n][h*8+d]
__device__ float g_Who[B*N*DOUT];         // [b][n][d]
__device__ float g_g1[B*N];
__device__ float g_g2[B*N];
__device__ float g_out[B*N*DOUT];         // post-elu, [b][n*32+d] = [b][k]
__device__ float g_qpart[128*B*N];        // split-K partials
__device__ int   g_cnt[B*N];              // neighbor counts
__device__ int   g_nbr[B*N*N];            // compacted neighbor lists

// ---------------- helpers ----------------
__device__ __forceinline__ float warpSum(float v){
#pragma unroll
    for (int o = 16; o; o >>= 1) v += __shfl_xor_sync(0xffffffffu, v, o);
    return v;
}
__device__ __forceinline__ float warpMax(float v){
#pragma unroll
    for (int o = 16; o; o >>= 1) v = fmaxf(v, __shfl_xor_sync(0xffffffffu, v, o));
    return v;
}
__device__ __forceinline__ float lrelu(float x){ return x >= 0.f ? x : 0.2f * x; }
__device__ __forceinline__ float elu(float x){ return x > 0.f ? x : expm1f(x); }

__device__ __forceinline__ ull fma2(ull a, ull b, ull c){
    ull d;
    asm("fma.rn.f32x2 %0, %1, %2, %3;" : "=l"(d) : "l"(a), "l"(b), "l"(c));
    return d;
}
__device__ __forceinline__ ull pack2(float x){
    ull r;
    asm("mov.b64 %0, {%1, %1};" : "=l"(r) : "f"(x));
    return r;
}
__device__ __forceinline__ void unpack2(ull v, float& lo, float& hi){
    asm("mov.b64 {%0, %1}, %2;" : "=f"(lo), "=f"(hi) : "l"(v));
}

// ---------------- K0: compact adjacency rows into neighbor lists ----------------
__global__ void k0_compact(const float* __restrict__ adj){
    int t = threadIdx.x, w = t >> 5, lane = t & 31;
    int row = blockIdx.x * 8 + w;
    const float* arow = adj + (size_t)row * N;
    float av[16];
#pragma unroll
    for (int c = 0; c < 16; c++) av[c] = arow[c*32 + lane];
    unsigned bal[16];
#pragma unroll
    for (int c = 0; c < 16; c++) bal[c] = __ballot_sync(0xffffffffu, av[c] > 0.f);
    int* dst = g_nbr + (size_t)row * N;
    int base = 0;
    unsigned lmask = (1u << lane) - 1u;
#pragma unroll
    for (int c = 0; c < 16; c++){
        unsigned b = bal[c];
        if ((b >> lane) & 1u) dst[base + __popc(b & lmask)] = c*32 + lane;
        base += __popc(b);
    }
    if (lane == 0) g_cnt[row] = base;
}

// ---------------- K1: Wh = xv @ W_heads ; f1 = Wh.a1 ; f2 = Wh.a2 ----------------
__global__ void k1_proj(const float* __restrict__ xv,
                        const float* __restrict__ Wheads,
                        const float* __restrict__ a1,
                        const float* __restrict__ a2){
    __shared__ float Ws[H*FIN*DH];
    __shared__ float a1s[H*DH], a2s[H*DH];
    int t = threadIdx.x;
    for (int i = t; i < H*FIN*DH; i += 256) Ws[i] = Wheads[i];
    if (t < H*DH){ a1s[t] = a1[t]; a2s[t] = a2[t]; }
    __syncthreads();

    int gt = blockIdx.x * 256 + t;
    int h  = gt & 7;
    int bn = gt >> 3;
    const float* xr = xv + bn * FIN;

    float wh[DH];
#pragma unroll
    for (int d = 0; d < DH; d++) wh[d] = 0.f;
#pragma unroll
    for (int f = 0; f < FIN; f++){
        float x = xr[f];
        const float* wf = Ws + (h*FIN + f)*DH;
#pragma unroll
        for (int d = 0; d < DH; d++) wh[d] += x * wf[d];
    }
    float f1v = 0.f, f2v = 0.f;
#pragma unroll
    for (int d = 0; d < DH; d++){
        f1v += wh[d] * a1s[h*DH + d];
        f2v += wh[d] * a2s[h*DH + d];
    }
    int b = bn >> 9, n = bn & 511;
    int bh = b*H + h;
    float* dstp = g_Wh + ((size_t)bh * N + n) * DH;
    ((float4*)dstp)[0] = make_float4(wh[0], wh[1], wh[2], wh[3]);
    ((float4*)dstp)[1] = make_float4(wh[4], wh[5], wh[6], wh[7]);
    g_f1[bh*N + n] = f1v;
    g_f2[bh*N + n] = f2v;
}

// ---------------- K2: layer-1 masked softmax + aggregation (warp = head) ----------------
__global__ void k2_gat(){
    int bi = blockIdx.x;            // = b*512 + i
    int t = threadIdx.x, w = t >> 5, lane = t & 31;
    int cnt = g_cnt[bi];
    const int* jl = g_nbr + (size_t)bi * N;

    int b = bi >> 9, i = bi & 511;
    int bh = b*H + w;
    const float* f2h = g_f2 + bh * N;
    const float* WhB = g_Wh + (size_t)bh * N * DH;
    float f1i = g_f1[bh*N + i];

    float s = 0.f;
    float pacc[DH];
#pragma unroll
    for (int d = 0; d < DH; d++) pacc[d] = 0.f;

    if (cnt > 0){
        float m = -1e30f;
        for (int k = lane; k < cnt; k += 32)
            m = fmaxf(m, lrelu(f1i + f2h[jl[k]]));
        m = warpMax(m);
        for (int k = lane; k < cnt; k += 32){
            int j = jl[k];
            float p = expf(lrelu(f1i + f2h[j]) - m);
            s += p;
            float4 wa = ((const float4*)(WhB + j*DH))[0];
            float4 wb = ((const float4*)(WhB + j*DH))[1];
            pacc[0] += p*wa.x; pacc[1] += p*wa.y; pacc[2] += p*wa.z; pacc[3] += p*wa.w;
            pacc[4] += p*wb.x; pacc[5] += p*wb.y; pacc[6] += p*wb.z; pacc[7] += p*wb.w;
        }
    } else {
        for (int j = lane; j < N; j += 32){
            s += 1.f;
            float4 wa = ((const float4*)(WhB + j*DH))[0];
            float4 wb = ((const float4*)(WhB + j*DH))[1];
            pacc[0] += wa.x; pacc[1] += wa.y; pacc[2] += wa.z; pacc[3] += wa.w;
            pacc[4] += wb.x; pacc[5] += wb.y; pacc[6] += wb.z; pacc[7] += wb.w;
        }
    }
    s = warpSum(s);
#pragma unroll
    for (int d = 0; d < DH; d++) pacc[d] = warpSum(pacc[d]);

    if (lane == 0){
        float inv = 1.f / s;
        float* o = g_hcat + (size_t)bi * (H*DH) + w * DH;
        ((float4*)o)[0] = make_float4(elu(pacc[0]*inv), elu(pacc[1]*inv), elu(pacc[2]*inv), elu(pacc[3]*inv));
        ((float4*)o)[1] = make_float4(elu(pacc[4]*inv), elu(pacc[5]*inv), elu(pacc[6]*inv), elu(pacc[7]*inv));
    }
}

// ---------------- K3: Who = h_cat @ W_out (64 rows/block) ; g1 ; g2 ----------------
__global__ void k3_who(const float* __restrict__ Wout,
                       const float* __restrict__ a1o,
                       const float* __restrict__ a2o){
    __shared__ float Ws[64*32];     // 8 KB, loaded ONCE per 64 rows
    __shared__ float hs[64*64];     // 16 KB
    __shared__ float a1s[32], a2s[32];
    int t = threadIdx.x;
    for (int i = t; i < 64*32; i += 256) Ws[i] = Wout[i];
    if (t < 32){ a1s[t] = a1o[t]; a2s[t] = a2o[t]; }
    const float4* src = (const float4*)(g_hcat + (size_t)blockIdx.x * 64 * 64);
    float4* hd = (float4*)hs;
    for (int i = t; i < 64*16; i += 256) hd[i] = src[i];
    __syncthreads();

    int w = t >> 5, lane = t & 31;
    float who[8];
#pragma unroll
    for (int r = 0; r < 8; r++) who[r] = 0.f;
    const float* hrow = hs + (w*8)*64;
#pragma unroll
    for (int f = 0; f < 64; f++){
        float wsv = Ws[f*32 + lane];
#pragma unroll
        for (int r = 0; r < 8; r++) who[r] += hrow[r*64 + f] * wsv;
    }
    int row0 = blockIdx.x*64 + w*8;
    float a1v = a1s[lane], a2v = a2s[lane];
#pragma unroll
    for (int r = 0; r < 8; r++){
        g_Who[(size_t)(row0+r)*32 + lane] = who[r];
        float v1 = warpSum(who[r]*a1v);
        float v2 = warpSum(who[r]*a2v);
        if (lane == 0){ g_g1[row0+r] = v1; g_g2[row0+r] = v2; }
    }
}

// ---------------- K4: layer-2 masked softmax + aggregation (warp per row, lane = dim) ----------------
__global__ void k4_outattn(){
    int t = threadIdx.x, w = t >> 5, lane = t & 31;
    int row = blockIdx.x * 8 + w;       // = b*512 + i
    int b = row >> 9;
    int cnt = g_cnt[row];
    const int* jl = g_nbr + (size_t)row * N;

    float g1i = g_g1[row];
    const float* g2b  = g_g2 + b * N;
    const float* WhoB = g_Who + (size_t)b * N * DOUT;

    float s = 0.f, tot = 0.f;
    if (cnt > 0){
        float m = -1e30f;
        for (int k = lane; k < cnt; k += 32)
            m = fmaxf(m, lrelu(g1i + g2b[jl[k]]));
        m = warpMax(m);
        for (int base = 0; base < cnt; base += 32){
            int k = base + lane;
            float p = 0.f; int j = 0;
            if (k < cnt){ j = jl[k]; p = expf(lrelu(g1i + g2b[j]) - m); }
            s += p;
            int lim = min(32, cnt - base);
            for (int kk = 0; kk < lim; kk++){
                float pb = __shfl_sync(0xffffffffu, p, kk);
                int   jb = __shfl_sync(0xffffffffu, j, kk);
                tot += pb * WhoB[(size_t)jb*DOUT + lane];
            }
        }
        s = warpSum(s);
    } else {
        s = (float)N;
        for (int j = 0; j < N; j++) tot += WhoB[(size_t)j*DOUT + lane];
    }
    g_out[(size_t)row*DOUT + lane] = elu(tot / s);
}

// ---------------- K5: q_part = out[B,16384] @ W_q[16384,512] (split-K 32-way, f32x2) ----------------
__global__ void k5_qgemm(const float* __restrict__ Wq){
    __shared__ float sm[256*36];        // 36 KB, [k_local][b] pad 36
    int t = threadIdx.x;
    int c = blockIdx.x * 64 + (t & 63);
    int g = t >> 6;                     // 0..3
    ull acc2[16];
#pragma unroll
    for (int q = 0; q < 16; q++) acc2[q] = 0ull;

    int kb0 = blockIdx.y * 512;
    for (int st = 0; st < 2; st++){
        int kbase = kb0 + st*256;
        __syncthreads();
        for (int idx = t; idx < 2048; idx += 256){
            int b  = idx >> 6;
            int kq = idx & 63;
            float4 v = *(const float4*)(g_out + (size_t)b*16384 + kbase + kq*4);
            float* dst = sm + kq*4*36 + b;
            dst[0]   = v.x; dst[36]  = v.y; dst[72]  = v.z; dst[108] = v.w;
        }
        __syncthreads();

        const float* wq  = Wq + (size_t)(kbase + g*64)*512 + c;
        const float* smg = sm + (g*64)*36;
#pragma unroll 4
        for (int kk = 0; kk < 64; kk++){
            ull wv2 = pack2(wq[(size_t)kk*512]);
            const ull* o2 = (const ull*)(smg + kk*36);   // [b] pairs, 8B aligned
#pragma unroll
            for (int q = 0; q < 16; q++)
                acc2[q] = fma2(o2[q], wv2, acc2[q]);
        }
    }
    float* qp = g_qpart + (size_t)(blockIdx.y*4 + g) * (B*N);
#pragma unroll
    for (int q = 0; q < 16; q++){
        float lo, hi; unpack2(acc2[q], lo, hi);
        qp[(2*q)*N + c]   = lo;
        qp[(2*q+1)*N + c] = hi;
    }
}

// ---------------- K6: q = sum of 128 partials + b_q ----------------
__global__ void k6_reduce(const float* __restrict__ bq, float* __restrict__ q){
    int t = blockIdx.x * 256 + threadIdx.x;   // [0, 16384)
    int c = t & 511;
    float s = bq[c];
#pragma unroll
    for (int p = 0; p < 128; p++) s += g_qpart[(size_t)p*(B*N) + t];
    q[t] = s;
}

// ---------------- launch ----------------
extern "C" void kernel_launch(void* const* d_in, const int* in_sizes, int n_in,
                              void* d_out, int out_size){
    const float* xv    = (const float*)d_in[0];
    const float* adj   = (const float*)d_in[1];
    const float* Whead = (const float*)d_in[2];
    const float* a1    = (const float*)d_in[3];
    const float* a2    = (const float*)d_in[4];
    const float* Wout  = (const float*)d_in[5];
    const float* a1o   = (const float*)d_in[6];
    const float* a2o   = (const float*)d_in[7];
    const float* Wq    = (const float*)d_in[8];
    const float* bq    = (const float*)d_in[9];
    float* q = (float*)d_out;

    k0_compact<<<B*N/8, 256>>>(adj);
    k1_proj   <<<512, 256>>>(xv, Whead, a1, a2);
    k2_gat    <<<B*N, 256>>>();
    k3_who    <<<B*N/64, 256>>>(Wout, a1o, a2o);
    k4_outattn<<<B*N/8, 256>>>();
    k5_qgemm  <<<dim3(8, 32), 256>>>(Wq);
    k6_reduce <<<64, 256>>>(bq, q);
}

// round 7
// speedup vs baseline: 1.4641x; 1.1617x over previous
#include <cuda_runtime.h>
#include <math.h>

#define B 32
#define N 512
#define FIN 16
#define H 8
#define DH 8
#define DOUT 32

typedef unsigned long long ull;

// ---------------- scratch (static device arrays; no allocation) ----------------
__device__ float g_Wh[B*N*H*DH];          // [b][n][h*8+d]  (row-major 64 per node)
__device__ float g_f1[B*N*H];             // [b][n][h]
__device__ float g_f2[B*N*H];             // [b][n][h]
__device__ float g_hcat[B*N*H*DH];        // [b][n][h*8+d]
__device__ float g_Who[B*N*DOUT];         // [b][n][d]
__device__ float g_g1[B*N];
__device__ float g_g2[B*N];
__device__ float g_out[B*N*DOUT];         // post-elu, [b][n*32+d] = [b][k]
__device__ float g_qpart[128*B*N];        // split-K partials
__device__ int   g_cnt[B*N];              // neighbor counts
__device__ int   g_nbr[B*N*N];            // compacted neighbor lists

// ---------------- helpers ----------------
__device__ __forceinline__ float warpSum(float v){
#pragma unroll
    for (int o = 16; o; o >>= 1) v += __shfl_xor_sync(0xffffffffu, v, o);
    return v;
}
__device__ __forceinline__ float lrelu(float x){ return x >= 0.f ? x : 0.2f * x; }
__device__ __forceinline__ float elu(float x){ return x > 0.f ? x : expm1f(x); }

__device__ __forceinline__ ull fma2(ull a, ull b, ull c){
    ull d;
    asm("fma.rn.f32x2 %0, %1, %2, %3;" : "=l"(d) : "l"(a), "l"(b), "l"(c));
    return d;
}
__device__ __forceinline__ ull pack2(float x){
    ull r;
    asm("mov.b64 %0, {%1, %1};" : "=l"(r) : "f"(x));
    return r;
}
__device__ __forceinline__ void unpack2(ull v, float& lo, float& hi){
    asm("mov.b64 {%0, %1}, %2;" : "=f"(lo), "=f"(hi) : "l"(v));
}

// ---------------- K0: compact adjacency rows into neighbor lists ----------------
__global__ void k0_compact(const float* __restrict__ adj){
    int t = threadIdx.x, w = t >> 5, lane = t & 31;
    int row = blockIdx.x * 8 + w;
    const float* arow = adj + (size_t)row * N;
    float av[16];
#pragma unroll
    for (int c = 0; c < 16; c++) av[c] = arow[c*32 + lane];
    unsigned bal[16];
#pragma unroll
    for (int c = 0; c < 16; c++) bal[c] = __ballot_sync(0xffffffffu, av[c] > 0.f);
    int* dst = g_nbr + (size_t)row * N;
    int base = 0;
    unsigned lmask = (1u << lane) - 1u;
#pragma unroll
    for (int c = 0; c < 16; c++){
        unsigned b = bal[c];
        if ((b >> lane) & 1u) dst[base + __popc(b & lmask)] = c*32 + lane;
        base += __popc(b);
    }
    if (lane == 0) g_cnt[row] = base;
}

// ---------------- K1: Wh = xv @ W_heads ; f1 ; f2  (node-major layouts) ----------------
__global__ void k1_proj(const float* __restrict__ xv,
                        const float* __restrict__ Wheads,
                        const float* __restrict__ a1,
                        const float* __restrict__ a2){
    __shared__ float Ws[H*FIN*DH];
    __shared__ float a1s[H*DH], a2s[H*DH];
    int t = threadIdx.x;
    for (int i = t; i < H*FIN*DH; i += 256) Ws[i] = Wheads[i];
    if (t < H*DH){ a1s[t] = a1[t]; a2s[t] = a2[t]; }
    __syncthreads();

    int gt = blockIdx.x * 256 + t;
    int h  = gt & 7;
    int bn = gt >> 3;
    const float* xr = xv + bn * FIN;

    float wh[DH];
#pragma unroll
    for (int d = 0; d < DH; d++) wh[d] = 0.f;
#pragma unroll
    for (int f = 0; f < FIN; f++){
        float x = xr[f];
        const float* wf = Ws + (h*FIN + f)*DH;
#pragma unroll
        for (int d = 0; d < DH; d++) wh[d] += x * wf[d];
    }
    float f1v = 0.f, f2v = 0.f;
#pragma unroll
    for (int d = 0; d < DH; d++){
        f1v += wh[d] * a1s[h*DH + d];
        f2v += wh[d] * a2s[h*DH + d];
    }
    float* dstp = g_Wh + (size_t)bn*64 + h*8;
    ((float4*)dstp)[0] = make_float4(wh[0], wh[1], wh[2], wh[3]);
    ((float4*)dstp)[1] = make_float4(wh[4], wh[5], wh[6], wh[7]);
    g_f1[bn*8 + h] = f1v;
    g_f2[bn*8 + h] = f2v;
}

// ---------------- K2: layer-1 attention, thread = (h,d), redundant softmax, no reductions ----------------
__global__ void k2_gat(){
    int t = threadIdx.x;
    int g = t >> 6, u = t & 63;         // 4 rows per block, 64 threads per row
    int h = u >> 3;                     // head
    int row = blockIdx.x * 4 + g;       // = b*512 + i
    int b = row >> 9;

    int cnt = g_cnt[row];
    const int* __restrict__ jl = g_nbr + (size_t)row * N;
    const float* __restrict__ f2B = g_f2 + (size_t)b * N * 8;
    const float* __restrict__ WhB = g_Wh + (size_t)b * N * 64;
    float f1i = g_f1[row*8 + h];

    float s = 0.f, acc = 0.f;
    if (cnt > 0){
        float m = -1e30f;
        for (int k = 0; k < cnt; k++)
            m = fmaxf(m, lrelu(f1i + f2B[jl[k]*8 + h]));
        for (int k = 0; k < cnt; k++){
            int j = jl[k];
            float p = expf(lrelu(f1i + f2B[j*8 + h]) - m);
            s += p;
            acc += p * WhB[(size_t)j*64 + u];
        }
    } else {
        s = (float)N;
        for (int j = 0; j < N; j++) acc += WhB[(size_t)j*64 + u];
    }
    g_hcat[(size_t)row*64 + u] = elu(acc / s);
}

// ---------------- K3: Who = h_cat @ W_out (64 rows/block, float4) ; g1 ; g2 ----------------
__global__ void k3_who(const float* __restrict__ Wout,
                       const float* __restrict__ a1o,
                       const float* __restrict__ a2o){
    __shared__ float Ws[64*32];     // 8 KB
    __shared__ float hs[64*64];     // 16 KB
    __shared__ float a1s[32], a2s[32];
    int t = threadIdx.x;
    for (int i = t; i < 64*32; i += 256) Ws[i] = Wout[i];
    if (t < 32){ a1s[t] = a1o[t]; a2s[t] = a2o[t]; }
    const float4* src = (const float4*)(g_hcat + (size_t)blockIdx.x * 64 * 64);
    float4* hd = (float4*)hs;
    for (int i = t; i < 64*16; i += 256) hd[i] = src[i];
    __syncthreads();

    int w = t >> 5, lane = t & 31;
    float who[8];
#pragma unroll
    for (int r = 0; r < 8; r++) who[r] = 0.f;
    const float4* hrow4 = (const float4*)(hs + (w*8)*64);
#pragma unroll
    for (int f4 = 0; f4 < 16; f4++){
        float w0 = Ws[(4*f4+0)*32 + lane];
        float w1 = Ws[(4*f4+1)*32 + lane];
        float w2 = Ws[(4*f4+2)*32 + lane];
        float w3 = Ws[(4*f4+3)*32 + lane];
#pragma unroll
        for (int r = 0; r < 8; r++){
            float4 hv = hrow4[r*16 + f4];
            who[r] += hv.x*w0 + hv.y*w1 + hv.z*w2 + hv.w*w3;
        }
    }
    int row0 = blockIdx.x*64 + w*8;
    float a1v = a1s[lane], a2v = a2s[lane];
    float v1[8], v2[8];
#pragma unroll
    for (int r = 0; r < 8; r++){
        g_Who[(size_t)(row0+r)*32 + lane] = who[r];
        v1[r] = who[r]*a1v; v2[r] = who[r]*a2v;
    }
#pragma unroll
    for (int o = 16; o; o >>= 1)
#pragma unroll
        for (int r = 0; r < 8; r++){
            v1[r] += __shfl_xor_sync(0xffffffffu, v1[r], o);
            v2[r] += __shfl_xor_sync(0xffffffffu, v2[r], o);
        }
    if (lane == 0)
#pragma unroll
        for (int r = 0; r < 8; r++){ g_g1[row0+r] = v1[r]; g_g2[row0+r] = v2[r]; }
}

// ---------------- K4: layer-2 attention, lane = dim, redundant softmax ----------------
__global__ void k4_outattn(){
    int t = threadIdx.x, w = t >> 5, lane = t & 31;
    int row = blockIdx.x * 8 + w;       // = b*512 + i
    int b = row >> 9;
    int cnt = g_cnt[row];
    const int* __restrict__ jl = g_nbr + (size_t)row * N;

    float g1i = g_g1[row];
    const float* __restrict__ g2b  = g_g2 + b * N;
    const float* __restrict__ WhoB = g_Who + (size_t)b * N * DOUT;

    float s = 0.f, tot = 0.f;
    if (cnt > 0){
        float m = -1e30f;
        for (int k = 0; k < cnt; k++)
            m = fmaxf(m, lrelu(g1i + g2b[jl[k]]));
        for (int k = 0; k < cnt; k++){
            int j = jl[k];
            float p = expf(lrelu(g1i + g2b[j]) - m);
            s += p;
            tot += p * WhoB[(size_t)j*DOUT + lane];
        }
    } else {
        s = (float)N;
        for (int j = 0; j < N; j++) tot += WhoB[(size_t)j*DOUT + lane];
    }
    g_out[(size_t)row*DOUT + lane] = elu(tot / s);
}

// ---------------- K5: q_part = out[B,16384] @ W_q[16384,512] (split-K 32-way, f32x2) ----------------
__global__ void k5_qgemm(const float* __restrict__ Wq){
    __shared__ float sm[256*36];        // 36 KB, [k_local][b] pad 36
    int t = threadIdx.x;
    int c = blockIdx.x * 64 + (t & 63);
    int g = t >> 6;                     // 0..3
    ull acc2[16];
#pragma unroll
    for (int q = 0; q < 16; q++) acc2[q] = 0ull;

    int kb0 = blockIdx.y * 512;
    for (int st = 0; st < 2; st++){
        int kbase = kb0 + st*256;
        __syncthreads();
        for (int idx = t; idx < 2048; idx += 256){
            int b  = idx >> 6;
            int kq = idx & 63;
            float4 v = *(const float4*)(g_out + (size_t)b*16384 + kbase + kq*4);
            float* dst = sm + kq*4*36 + b;
            dst[0]   = v.x; dst[36]  = v.y; dst[72]  = v.z; dst[108] = v.w;
        }
        __syncthreads();

        const float* wq  = Wq + (size_t)(kbase + g*64)*512 + c;
        const float* smg = sm + (g*64)*36;
#pragma unroll 4
        for (int kk = 0; kk < 64; kk++){
            ull wv2 = pack2(wq[(size_t)kk*512]);
            const ull* o2 = (const ull*)(smg + kk*36);
#pragma unroll
            for (int q = 0; q < 16; q++)
                acc2[q] = fma2(o2[q], wv2, acc2[q]);
        }
    }
    float* qp = g_qpart + (size_t)(blockIdx.y*4 + g) * (B*N);
#pragma unroll
    for (int q = 0; q < 16; q++){
        float lo, hi; unpack2(acc2[q], lo, hi);
        qp[(2*q)*N + c]   = lo;
        qp[(2*q+1)*N + c] = hi;
    }
}

// ---------------- K6: q = sum of 128 partials + b_q ----------------
__global__ void k6_reduce(const float* __restrict__ bq, float* __restrict__ q){
    int t = blockIdx.x * 128 + threadIdx.x;   // [0, 16384)
    int c = t & 511;
    float s = bq[c];
#pragma unroll
    for (int p = 0; p < 128; p++) s += g_qpart[(size_t)p*(B*N) + t];
    q[t] = s;
}

// ---------------- launch ----------------
extern "C" void kernel_launch(void* const* d_in, const int* in_sizes, int n_in,
                              void* d_out, int out_size){
    const float* xv    = (const float*)d_in[0];
    const float* adj   = (const float*)d_in[1];
    const float* Whead = (const float*)d_in[2];
    const float* a1    = (const float*)d_in[3];
    const float* a2    = (const float*)d_in[4];
    const float* Wout  = (const float*)d_in[5];
    const float* a1o   = (const float*)d_in[6];
    const float* a2o   = (const float*)d_in[7];
    const float* Wq    = (const float*)d_in[8];
    const float* bq    = (const float*)d_in[9];
    float* q = (float*)d_out;

    k0_compact<<<B*N/8, 256>>>(adj);
    k1_proj   <<<512, 256>>>(xv, Whead, a1, a2);
    k2_gat    <<<B*N/4, 256>>>();
    k3_who    <<<B*N/64, 256>>>(Wout, a1o, a2o);
    k4_outattn<<<B*N/8, 256>>>();
    k5_qgemm  <<<dim3(8, 32), 256>>>(Wq);
    k6_reduce <<<128, 128>>>(bq, q);
}